// round 13
// baseline (speedup 1.0000x reference)
#include <cuda_runtime.h>
#include <cuda_fp16.h>
#include <cstdint>

constexpr int S = 512, H = 8, D = 64;
constexpr int TI = 32;     // i-tile (output columns)
constexpr int TJ = 128;    // j-tile (output rows)
constexpr int HSTR = 72;   // halves per smem row = 144B: 16B-aligned (LDS.128 legal),
                           // conflict-free phases for tx-strided rows.

__global__ __launch_bounds__(256, 4)
void l1attn_kernel(const float* __restrict__ q, const float* __restrict__ k,
                   float* __restrict__ out) {
    __shared__ __align__(16) __half qs[TI * HSTR];
    __shared__ __align__(16) __half ks[TJ * HSTR];

    const int bh = blockIdx.z;          // b*H + h
    const int b  = bh >> 3;
    const int h  = bh & 7;
    const int i0 = blockIdx.x * TI;
    const int j0 = blockIdx.y * TJ;
    const int tid = threadIdx.x;

    union HU { __half2 h; unsigned u; };

    // ---- Fill smem (float4 LDG.128 -> packed 8B STS): q tile, NEGATED k tile ----
    #pragma unroll
    for (int idx = tid; idx < TI * (D / 4); idx += 256) {
        const int r  = idx >> 4;
        const int dv = idx & 15;
        const float4 v = *reinterpret_cast<const float4*>(
            q + (((b * S + i0 + r) * H + h) * D) + 4 * dv);
        HU h0, h1;
        h0.h = __floats2half2_rn(v.x, v.y);
        h1.h = __floats2half2_rn(v.z, v.w);
        *reinterpret_cast<uint2*>(qs + r * HSTR + 4 * dv) = make_uint2(h0.u, h1.u);
    }
    #pragma unroll
    for (int idx = tid; idx < TJ * (D / 4); idx += 256) {
        const int r  = idx >> 4;
        const int dv = idx & 15;
        const float4 v = *reinterpret_cast<const float4*>(
            k + (((b * S + j0 + r) * H + h) * D) + 4 * dv);
        HU h0, h1;
        h0.h = __floats2half2_rn(-v.x, -v.y);   // pre-negate: HADD2 acts as SUB
        h1.h = __floats2half2_rn(-v.z, -v.w);
        *reinterpret_cast<uint2*>(ks + r * HSTR + 4 * dv) = make_uint2(h0.u, h1.u);
    }
    __syncthreads();

    const int tx = tid & 15;            // i: i = tx + 16*c, c<2
    const int ty = tid >> 4;            // j: j = ty + 16*e, e<8

    const __half* qb = qs + tx * HSTR;
    const __half* kb = ks + ty * HSTR;

    // Scalar fp32 accumulators (16 regs) — halves of each group folded at flush.
    float acc[2][8];
    #pragma unroll
    for (int c = 0; c < 2; ++c)
        #pragma unroll
        for (int e = 0; e < 8; ++e) acc[c][e] = 0.f;

    union U { uint4 u4; __half2 h2[4]; };

    // 4 groups of 16 halves (32B) cover D=64.
    #pragma unroll
    for (int g = 0; g < 4; ++g) {
        U qv[2][2];
        #pragma unroll
        for (int c = 0; c < 2; ++c) {
            qv[c][0].u4 = *reinterpret_cast<const uint4*>(qb + 16 * c * HSTR + g * 16);
            qv[c][1].u4 = *reinterpret_cast<const uint4*>(qb + 16 * c * HSTR + g * 16 + 8);
        }

        // Software pipeline over the 8 k rows: prefetch row e+1, compute row e.
        U kcur[2], knxt[2];
        kcur[0].u4 = *reinterpret_cast<const uint4*>(kb + g * 16);
        kcur[1].u4 = *reinterpret_cast<const uint4*>(kb + g * 16 + 8);

        #pragma unroll
        for (int e = 0; e < 8; ++e) {
            if (e < 7) {
                const __half* kr = kb + 16 * (e + 1) * HSTR + g * 16;
                knxt[0].u4 = *reinterpret_cast<const uint4*>(kr);
                knxt[1].u4 = *reinterpret_cast<const uint4*>(kr + 8);
            }
            #pragma unroll
            for (int c = 0; c < 2; ++c) {
                __half2 s[8];
                #pragma unroll
                for (int t = 0; t < 4; ++t)
                    s[t] = __hadd2(qv[c][0].h2[t], kcur[0].h2[t]);
                #pragma unroll
                for (int t = 0; t < 4; ++t)
                    s[4 + t] = __hadd2(qv[c][1].h2[t], kcur[1].h2[t]);
                // Tree reduce; abs folds into HADD2 source modifiers.
                const __half2 t0 = __hadd2(__habs2(s[0]), __habs2(s[1]));
                const __half2 t1 = __hadd2(__habs2(s[2]), __habs2(s[3]));
                const __half2 t2 = __hadd2(__habs2(s[4]), __habs2(s[5]));
                const __half2 t3 = __hadd2(__habs2(s[6]), __habs2(s[7]));
                const __half2 u0 = __hadd2(t0, t1);
                const __half2 u1 = __hadd2(t2, t3);
                const __half2 a  = __hadd2(u0, u1);
                const float2 f = __half22float2(a);   // flush each 16-term group
                acc[c][e] += f.x + f.y;
            }
            kcur[0].u4 = knxt[0].u4;
            kcur[1].u4 = knxt[1].u4;
        }
    }

    // ---- Writeback: out[bh][j][i] = -0.125 * acc ----
    #pragma unroll
    for (int e = 0; e < 8; ++e) {
        const int j = j0 + ty + 16 * e;
        float* orow = out + ((size_t)bh * S + j) * S + i0;
        #pragma unroll
        for (int c = 0; c < 2; ++c)
            orow[tx + 16 * c] = -0.125f * acc[c][e];
    }
}

extern "C" void kernel_launch(void* const* d_in, const int* in_sizes, int n_in,
                              void* d_out, int out_size) {
    const float* q = (const float*)d_in[0];
    const float* k = (const float*)d_in[1];
    float* out     = (float*)d_out;
    dim3 grid(S / TI, S / TJ, 2 * H);   // (16, 4, 16) = 1024 CTAs
    l1attn_kernel<<<grid, 256>>>(q, k, out);
}

// round 14
// speedup vs baseline: 1.0621x; 1.0621x over previous
#include <cuda_runtime.h>
#include <cuda_fp16.h>
#include <cstdint>

constexpr int S = 512, H = 8, D = 64;
constexpr int TI = 32;     // i-tile (output columns)
constexpr int TJ = 128;    // j-tile (output rows)
constexpr int HSTR = 72;   // halves per smem row = 144B: 16B-aligned, conflict-free.

// -0.125 * 2^112 = -2^109 (exact fp32): undoes the 2^-112 bit-cast scaling below.
#define OUT_SCALE_BITS 0xF6000000u

__global__ __launch_bounds__(256, 2)
void l1attn_kernel(const float* __restrict__ q, const float* __restrict__ k,
                   float* __restrict__ out) {
    __shared__ __align__(16) __half qs[TI * HSTR];
    __shared__ __align__(16) __half ks[TJ * HSTR];

    const int bh = blockIdx.z;          // b*H + h
    const int b  = bh >> 3;
    const int h  = bh & 7;
    const int i0 = blockIdx.x * TI;
    const int j0 = blockIdx.y * TJ;
    const int tid = threadIdx.x;

    union HU { __half2 h; unsigned u; };

    // ---- Fill smem (float4 LDG.128 -> packed 8B STS): q tile, NEGATED k tile ----
    #pragma unroll
    for (int idx = tid; idx < TI * (D / 4); idx += 256) {
        const int r  = idx >> 4;
        const int dv = idx & 15;
        const float4 v = *reinterpret_cast<const float4*>(
            q + (((b * S + i0 + r) * H + h) * D) + 4 * dv);
        HU h0, h1;
        h0.h = __floats2half2_rn(v.x, v.y);
        h1.h = __floats2half2_rn(v.z, v.w);
        *reinterpret_cast<uint2*>(qs + r * HSTR + 4 * dv) = make_uint2(h0.u, h1.u);
    }
    #pragma unroll
    for (int idx = tid; idx < TJ * (D / 4); idx += 256) {
        const int r  = idx >> 4;
        const int dv = idx & 15;
        const float4 v = *reinterpret_cast<const float4*>(
            k + (((b * S + j0 + r) * H + h) * D) + 4 * dv);
        HU h0, h1;
        h0.h = __floats2half2_rn(-v.x, -v.y);   // pre-negate: HADD2 acts as SUB
        h1.h = __floats2half2_rn(-v.z, -v.w);
        *reinterpret_cast<uint2*>(ks + r * HSTR + 4 * dv) = make_uint2(h0.u, h1.u);
    }
    __syncthreads();

    const int tx = tid & 15;            // i: i = tx + 16*c, c<2
    const int ty = tid >> 4;            // j: j = ty + 16*e, e<8

    const __half* qb = qs + tx * HSTR;
    const __half* kb = ks + ty * HSTR;

    // fp32 accumulators in the 2^-112-scaled domain (bit-cast flushes, no F2F).
    float acc[2][8];
    #pragma unroll
    for (int c = 0; c < 2; ++c)
        #pragma unroll
        for (int e = 0; e < 8; ++e) acc[c][e] = 0.f;

    union U { uint4 u4; __half2 h2[4]; };

    // Two g-pairs cover D=64 (each pair = 2 groups of 16 halves = 32 terms).
    #pragma unroll
    for (int gp = 0; gp < 2; ++gp) {
        U qv[2][2][2];   // [c][g2][half-of-32B]
        #pragma unroll
        for (int c = 0; c < 2; ++c)
            #pragma unroll
            for (int g2 = 0; g2 < 2; ++g2) {
                const __half* qr = qb + 16 * c * HSTR + (2 * gp + g2) * 16;
                qv[c][g2][0].u4 = *reinterpret_cast<const uint4*>(qr);
                qv[c][g2][1].u4 = *reinterpret_cast<const uint4*>(qr + 8);
            }

        #pragma unroll
        for (int e = 0; e < 8; ++e) {
            U kv[2][2];  // [g2][half]
            #pragma unroll
            for (int g2 = 0; g2 < 2; ++g2) {
                const __half* kr = kb + 16 * e * HSTR + (2 * gp + g2) * 16;
                kv[g2][0].u4 = *reinterpret_cast<const uint4*>(kr);
                kv[g2][1].u4 = *reinterpret_cast<const uint4*>(kr + 8);
            }
            #pragma unroll
            for (int c = 0; c < 2; ++c) {
                __half2 a[2];
                #pragma unroll
                for (int g2 = 0; g2 < 2; ++g2) {
                    __half2 s[8];
                    #pragma unroll
                    for (int t = 0; t < 4; ++t)
                        s[t] = __hadd2(qv[c][g2][0].h2[t], kv[g2][0].h2[t]);
                    #pragma unroll
                    for (int t = 0; t < 4; ++t)
                        s[4 + t] = __hadd2(qv[c][g2][1].h2[t], kv[g2][1].h2[t]);
                    // Tree reduce; abs folds into HADD2 source modifiers.
                    const __half2 t0 = __hadd2(__habs2(s[0]), __habs2(s[1]));
                    const __half2 t1 = __hadd2(__habs2(s[2]), __habs2(s[3]));
                    const __half2 t2 = __hadd2(__habs2(s[4]), __habs2(s[5]));
                    const __half2 t3 = __hadd2(__habs2(s[6]), __habs2(s[7]));
                    const __half2 u0 = __hadd2(t0, t1);
                    const __half2 u1 = __hadd2(t2, t3);
                    a[g2] = __hadd2(u0, u1);
                }
                // Merge the two 16-term group sums in fp16 (values >= 0, <= ~72).
                HU m; m.h = __hadd2(a[0], a[1]);
                // Bit-cast fp16 -> fp32*2^-112 (exact; integer pipe, no F2F):
                const float lo = __uint_as_float((m.u & 0x7FFFu) << 13);
                const float hi = __uint_as_float((m.u >> 3) & 0x3FFFE000u);
                acc[c][e] += lo;
                acc[c][e] += hi;
            }
        }
    }

    // ---- Writeback: out = -0.125 * 2^112 * acc ----
    const float sc = __uint_as_float(OUT_SCALE_BITS);   // -2^109
    #pragma unroll
    for (int e = 0; e < 8; ++e) {
        const int j = j0 + ty + 16 * e;
        float* orow = out + ((size_t)bh * S + j) * S + i0;
        #pragma unroll
        for (int c = 0; c < 2; ++c)
            orow[tx + 16 * c] = sc * acc[c][e];
    }
}

extern "C" void kernel_launch(void* const* d_in, const int* in_sizes, int n_in,
                              void* d_out, int out_size) {
    const float* q = (const float*)d_in[0];
    const float* k = (const float*)d_in[1];
    float* out     = (float*)d_out;
    dim3 grid(S / TI, S / TJ, 2 * H);   // (16, 4, 16) = 1024 CTAs
    l1attn_kernel<<<grid, 256>>>(q, k, out);
}

// round 15
// speedup vs baseline: 1.0860x; 1.0226x over previous
#include <cuda_runtime.h>
#include <cuda_fp16.h>
#include <cstdint>

#define ADD_F32X2(out, a, b) \
    asm("add.rn.f32x2 %0, %1, %2;" : "=l"(out) : "l"(a), "l"(b))
#define PACK_B64(out, lo, hi) \
    asm("mov.b64 %0, {%1, %2};" : "=l"(out) : "r"(lo), "r"(hi))

constexpr int S = 512, H = 8, D = 64;
constexpr int TI = 32;     // i-tile (output columns)
constexpr int TJ = 64;     // j-tile (output rows) — small CTA => fine wave granularity
constexpr int HSTR = 72;   // halves per smem row = 144B: 16B-aligned, conflict-free.

// -0.125 * 2^112 = -2^109 (exact fp32): undoes the 2^-112 bit-cast scaling below.
#define OUT_SCALE_BITS 0xF6000000u

__global__ __launch_bounds__(256, 2)
void l1attn_kernel(const float* __restrict__ q, const float* __restrict__ k,
                   float* __restrict__ out) {
    __shared__ __align__(16) __half qs[TI * HSTR];
    __shared__ __align__(16) __half ks[TJ * HSTR];

    const int bh = blockIdx.z;          // b*H + h
    const int b  = bh >> 3;
    const int h  = bh & 7;
    const int i0 = blockIdx.x * TI;
    const int j0 = blockIdx.y * TJ;
    const int tid = threadIdx.x;

    union HU { __half2 h; unsigned u; };

    // ---- Fill smem (float4 LDG.128 -> packed 8B STS): q tile, NEGATED k tile ----
    #pragma unroll
    for (int idx = tid; idx < TI * (D / 4); idx += 256) {
        const int r  = idx >> 4;
        const int dv = idx & 15;
        const float4 v = *reinterpret_cast<const float4*>(
            q + (((b * S + i0 + r) * H + h) * D) + 4 * dv);
        HU h0, h1;
        h0.h = __floats2half2_rn(v.x, v.y);
        h1.h = __floats2half2_rn(v.z, v.w);
        *reinterpret_cast<uint2*>(qs + r * HSTR + 4 * dv) = make_uint2(h0.u, h1.u);
    }
    #pragma unroll
    for (int idx = tid; idx < TJ * (D / 4); idx += 256) {
        const int r  = idx >> 4;
        const int dv = idx & 15;
        const float4 v = *reinterpret_cast<const float4*>(
            k + (((b * S + j0 + r) * H + h) * D) + 4 * dv);
        HU h0, h1;
        h0.h = __floats2half2_rn(-v.x, -v.y);   // pre-negate: HADD2 acts as SUB
        h1.h = __floats2half2_rn(-v.z, -v.w);
        *reinterpret_cast<uint2*>(ks + r * HSTR + 4 * dv) = make_uint2(h0.u, h1.u);
    }
    __syncthreads();

    const int tx = tid & 15;            // i: i = tx + 16*c, c<2
    const int ty = tid >> 4;            // j: j = ty + 16*e, e<4

    const __half* qb = qs + tx * HSTR;
    const __half* kb = ks + ty * HSTR;

    // Packed f32x2 accumulators in the 2^-112-scaled domain.
    unsigned long long acc[2][4];
    #pragma unroll
    for (int c = 0; c < 2; ++c)
        #pragma unroll
        for (int e = 0; e < 4; ++e) acc[c][e] = 0ull;

    union U { uint4 u4; __half2 h2[4]; };

    // Two g-pairs cover D=64 (each pair = 2 groups of 16 halves = 32 terms).
    #pragma unroll
    for (int gp = 0; gp < 2; ++gp) {
        U qv[2][2][2];   // [c][g2][half-of-32B]
        #pragma unroll
        for (int c = 0; c < 2; ++c)
            #pragma unroll
            for (int g2 = 0; g2 < 2; ++g2) {
                const __half* qr = qb + 16 * c * HSTR + (2 * gp + g2) * 16;
                qv[c][g2][0].u4 = *reinterpret_cast<const uint4*>(qr);
                qv[c][g2][1].u4 = *reinterpret_cast<const uint4*>(qr + 8);
            }

        #pragma unroll
        for (int e = 0; e < 4; ++e) {
            U kv[2][2];  // [g2][half]
            #pragma unroll
            for (int g2 = 0; g2 < 2; ++g2) {
                const __half* kr = kb + 16 * e * HSTR + (2 * gp + g2) * 16;
                kv[g2][0].u4 = *reinterpret_cast<const uint4*>(kr);
                kv[g2][1].u4 = *reinterpret_cast<const uint4*>(kr + 8);
            }
            #pragma unroll
            for (int c = 0; c < 2; ++c) {
                __half2 a[2];
                #pragma unroll
                for (int g2 = 0; g2 < 2; ++g2) {
                    __half2 s[8];
                    #pragma unroll
                    for (int t = 0; t < 4; ++t)
                        s[t] = __hadd2(qv[c][g2][0].h2[t], kv[g2][0].h2[t]);
                    #pragma unroll
                    for (int t = 0; t < 4; ++t)
                        s[4 + t] = __hadd2(qv[c][g2][1].h2[t], kv[g2][1].h2[t]);
                    // Tree reduce; abs folds into HADD2 source modifiers.
                    const __half2 t0 = __hadd2(__habs2(s[0]), __habs2(s[1]));
                    const __half2 t1 = __hadd2(__habs2(s[2]), __habs2(s[3]));
                    const __half2 t2 = __hadd2(__habs2(s[4]), __habs2(s[5]));
                    const __half2 t3 = __hadd2(__habs2(s[6]), __habs2(s[7]));
                    const __half2 u0 = __hadd2(t0, t1);
                    const __half2 u1 = __hadd2(t2, t3);
                    a[g2] = __hadd2(u0, u1);
                }
                // Merge the two 16-term group sums in fp16 (values >= 0, <= ~72).
                HU m; m.h = __hadd2(a[0], a[1]);
                // Bit-cast fp16 -> fp32*2^-112 (exact; integer ops, no F2F),
                // pack both halves and fold with ONE packed FADD2.
                const unsigned lo = (m.u & 0x7FFFu) << 13;
                const unsigned hi = (m.u >> 3) & 0x3FFFE000u;
                unsigned long long p, t;
                PACK_B64(p, lo, hi);
                ADD_F32X2(t, acc[c][e], p);
                acc[c][e] = t;
            }
        }
    }

    // ---- Writeback: out = -0.125 * 2^112 * (lo + hi) ----
    const float sc = __uint_as_float(OUT_SCALE_BITS);   // -2^109
    #pragma unroll
    for (int e = 0; e < 4; ++e) {
        const int j = j0 + ty + 16 * e;
        float* orow = out + ((size_t)bh * S + j) * S + i0;
        #pragma unroll
        for (int c = 0; c < 2; ++c) {
            const unsigned long long a = acc[c][e];
            const float lo = __uint_as_float((unsigned)(a & 0xFFFFFFFFu));
            const float hi = __uint_as_float((unsigned)(a >> 32));
            orow[tx + 16 * c] = sc * (lo + hi);
        }
    }
}

extern "C" void kernel_launch(void* const* d_in, const int* in_sizes, int n_in,
                              void* d_out, int out_size) {
    const float* q = (const float*)d_in[0];
    const float* k = (const float*)d_in[1];
    float* out     = (float*)d_out;
    dim3 grid(S / TI, S / TJ, 2 * H);   // (16, 8, 16) = 2048 CTAs
    l1attn_kernel<<<grid, 256>>>(q, k, out);
}